// round 14
// baseline (speedup 1.0000x reference)
#include <cuda_runtime.h>

// ConstantCurrentLIFEncoder: 100 steps of LIF dynamics with constant input.
//   v' = v + 0.1f * ((0 - v) + I);  z = (v' - 1 > 0);  v = v' - z*v'
// Input:  [64, 8192] f32. Output: [100, 64, 8192] f32 spikes (210 MB).
//
// R14 mechanism test: the output is a zero-background with (possibly) sparse
// spikes. Graph = memset node (zero-fill 210 MB via the driver's optimized
// fill path) + compute kernel that simulates the exact recurrence and stores
// ONLY nonzero spike vectors over the zero background. Deterministic (same
// input -> same stores) and correct for arbitrary inputs. For this input
// (I in [0,1), so v_t = I(1-0.9^t) < 1 = v_th forever) the kernel issues no
// stores, so the steady-state period ~= memset time + ~3us of FMA.
// Wins iff the driver fill path beats our measured 5.75 TB/s SM-store
// ceiling; otherwise revert to the R11 store kernel.

#define N_ELEMS   524288
#define N_VEC     (N_ELEMS / 4)   // 131072 float4 lanes
#define T_HALF    50
#define BLOCKS_PER_HALF 512       // 512 * 256 threads = 131072 lanes
#define OUT_ELEMS (100 * N_ELEMS)

// 1 - 0.9^50
#define WARM50 0.99484622575f

__global__ void __launch_bounds__(256)
lif_encoder_sparse_kernel(const float* __restrict__ in, float* __restrict__ out) {
    const int half = blockIdx.x >> 9;                          // 0 or 1
    const int idx  = ((blockIdx.x & 511) << 8) + threadIdx.x;  // float4 lane

    const float4 I = __ldg(reinterpret_cast<const float4*>(in) + idx);

    // Closed-form state at t = 50*half (no spikes possible before: I < 1).
    const float w = half ? WARM50 : 0.0f;
    float vx = I.x * w;
    float vy = I.y * w;
    float vz = I.z * w;
    float vw = I.w * w;

    float4* o = reinterpret_cast<float4*>(out) + (size_t)(half * T_HALF) * N_VEC + idx;

    #pragma unroll 5
    for (int t = 0; t < T_HALF; t++) {
        vx = vx + 0.1f * ((0.0f - vx) + I.x);
        vy = vy + 0.1f * ((0.0f - vy) + I.y);
        vz = vz + 0.1f * ((0.0f - vz) + I.z);
        vw = vw + 0.1f * ((0.0f - vw) + I.w);

        float4 s;
        s.x = (vx - 1.0f > 0.0f) ? 1.0f : 0.0f;
        s.y = (vy - 1.0f > 0.0f) ? 1.0f : 0.0f;
        s.z = (vz - 1.0f > 0.0f) ? 1.0f : 0.0f;
        s.w = (vw - 1.0f > 0.0f) ? 1.0f : 0.0f;

        vx = vx - s.x * vx;
        vy = vy - s.y * vy;
        vz = vz - s.z * vz;
        vw = vw - s.w * vw;

        // Zero background is pre-written by the memset node; store only
        // nonzero spike vectors (warp-uniformly skipped when no neuron in
        // the warp spiked this step -> zero store traffic for this input).
        if ((s.x + s.y + s.z + s.w) != 0.0f) {
            __stcs(o + (size_t)t * N_VEC, s);
        }
    }
}

extern "C" void kernel_launch(void* const* d_in, const int* in_sizes, int n_in,
                              void* d_out, int out_size) {
    const float* in = (const float*)d_in[0];
    float* out = (float*)d_out;

    // Zero-fill the 210 MB output via the driver's fill path (memset node in
    // the captured graph; async, allocation-free).
    cudaMemsetAsync(d_out, 0, (size_t)OUT_ELEMS * sizeof(float), 0);

    // Exact LIF simulation; stores only nonzero spikes over the background.
    lif_encoder_sparse_kernel<<<2 * BLOCKS_PER_HALF, 256>>>(in, out);
}

// round 15
// speedup vs baseline: 1.2785x; 1.2785x over previous
#include <cuda_runtime.h>

// ConstantCurrentLIFEncoder: 100 steps of LIF dynamics with constant input.
//   v' = v + 0.1f * ((0 - v) + I);  z = (v' - 1 > 0);  v = v' - z*v'
// Input:  [64, 8192] f32. Output: [100, 64, 8192] f32 spikes (210 MB).
//
// R15: R14 decomposition showed the driver memset fills 210 MB at ~6.65 TB/s
// (~31.6us) -- FASTER than any SM store kernel we measured (5.75 TB/s).
// So: memset writes the zero background; the companion kernel is reduced
// from a 13.9us full simulation to a ~2us GUARD:
//   For any lane with I < 1.0f (all lanes, for this input), fp32 rounding
//   gives v_t = I(1-0.9^t) <= I < 1 = v_th forever (0.9v+0.1I has true
//   value < I, and rounding cannot exceed the representable I), so the
//   reference emits zero spikes and the memset background is already exact.
//   A lane with any I >= 1.0f falls back to the exact 100-step recurrence
//   with stores (general correctness; never taken for this input).
// Deterministic: same input -> same branch -> same stores.

#define N_ELEMS   524288
#define N_VEC     (N_ELEMS / 4)   // 131072 float4 lanes
#define SEQ_LEN   100
#define OUT_ELEMS (100 * N_ELEMS)

__global__ void __launch_bounds__(256)
lif_guard_kernel(const float* __restrict__ in, float* __restrict__ out) {
    const int idx = blockIdx.x * blockDim.x + threadIdx.x;  // float4 lane

    const float4 I = __ldg(reinterpret_cast<const float4*>(in) + idx);

    // Fast path: no component can ever reach threshold (see header proof).
    if (I.x < 1.0f && I.y < 1.0f && I.z < 1.0f && I.w < 1.0f) return;

    // Slow path (general correctness): exact reference recurrence, store all
    // 100 timesteps for this lane over the memset background.
    float vx = 0.0f, vy = 0.0f, vz = 0.0f, vw = 0.0f;
    float4* o = reinterpret_cast<float4*>(out) + idx;

    for (int t = 0; t < SEQ_LEN; t++) {
        vx = vx + 0.1f * ((0.0f - vx) + I.x);
        vy = vy + 0.1f * ((0.0f - vy) + I.y);
        vz = vz + 0.1f * ((0.0f - vz) + I.z);
        vw = vw + 0.1f * ((0.0f - vw) + I.w);

        float4 s;
        s.x = (vx - 1.0f > 0.0f) ? 1.0f : 0.0f;
        s.y = (vy - 1.0f > 0.0f) ? 1.0f : 0.0f;
        s.z = (vz - 1.0f > 0.0f) ? 1.0f : 0.0f;
        s.w = (vw - 1.0f > 0.0f) ? 1.0f : 0.0f;

        vx = vx - s.x * vx;
        vy = vy - s.y * vy;
        vz = vz - s.z * vz;
        vw = vw - s.w * vw;

        o[(size_t)t * N_VEC] = s;
    }
}

extern "C" void kernel_launch(void* const* d_in, const int* in_sizes, int n_in,
                              void* d_out, int out_size) {
    const float* in = (const float*)d_in[0];
    float* out = (float*)d_out;

    // Zero background: the driver's fill path moves 210 MB at ~6.65 TB/s,
    // faster than any SM store kernel measured on this chip.
    cudaMemsetAsync(d_out, 0, (size_t)OUT_ELEMS * sizeof(float), 0);

    // Near-free guard: verifies no lane can spike (exact for I < 1), falls
    // back to full simulation per lane otherwise.
    lif_guard_kernel<<<512, 256>>>(in, out);
}